// round 2
// baseline (speedup 1.0000x reference)
#include <cuda_runtime.h>

// AI4DEM coupling_backward: 3x3 tent-spline gather, 4096x4096 periodic grid.
// Inputs (metadata order): xp, yp, x_grid(unused), y_grid(unused), vx, vy, Fx, Fy, mask
// Output: 5 planes [alpha, alpha_u, alpha_v, Fx, Fy], each 4096*4096 f32.
//
// Reference reduces to (DX=DY=1, inv_area=1):
//   per tap: w = max(0,1-|xp_src - x_dst|) * max(0,1-|yp_src - y_dst|)
//   alpha   = mask_dst * VP * sum(w)                 <-- mask at DESTINATION
//   alpha_u = mask_dst * VP * sum(w * vx_src)   etc.
// So mask*VP is hoisted out of the 3x3 loop entirely and applied once at the
// end. Each thread computes 4 consecutive x outputs; the 6 source columns
// (x-1 .. x+4) are loaded once per row and shared across taps.

#define NXD 4096
#define MASKW 4095

__device__ __forceinline__ void load6(const float* __restrict__ p, size_t rb,
                                      int xb, int cl, int cr, float v[6]) {
    float4 q = *reinterpret_cast<const float4*>(p + rb + xb);
    v[0] = __ldg(p + rb + cl);
    v[1] = q.x; v[2] = q.y; v[3] = q.z; v[4] = q.w;
    v[5] = __ldg(p + rb + cr);
}

__global__ void __launch_bounds__(256)
ai4dem_kernel(const float* __restrict__ xp, const float* __restrict__ yp,
              const float* __restrict__ vx, const float* __restrict__ vy,
              const float* __restrict__ Fx, const float* __restrict__ Fy,
              const float* __restrict__ mk, float* __restrict__ out)
{
    const float VP = 3.1415f / 6.0f;

    int t  = blockIdx.x * blockDim.x + threadIdx.x;   // 4096*1024 threads
    int y  = t >> 10;                                 // row
    int xb = (t & 1023) << 2;                         // base column (multiple of 4)

    const float fy0 = (float)y;
    float xk0 = (float)xb;
    float xdst[4] = {xk0, xk0 + 1.0f, xk0 + 2.0f, xk0 + 3.0f};

    float aA[4] = {0.f, 0.f, 0.f, 0.f};
    float aU[4] = {0.f, 0.f, 0.f, 0.f};
    float aV[4] = {0.f, 0.f, 0.f, 0.f};
    float aX[4] = {0.f, 0.f, 0.f, 0.f};
    float aY[4] = {0.f, 0.f, 0.f, 0.f};

    int cl = (xb - 1) & MASKW;
    int cr = (xb + 4) & MASKW;

    #pragma unroll
    for (int r = 0; r < 3; ++r) {
        int ys = (y + r - 1) & MASKW;
        size_t rb = (size_t)ys << 12;

        float xps[6], yps[6], vxs[6], vys[6], fxs[6], fys[6];
        load6(xp, rb, xb, cl, cr, xps);
        load6(yp, rb, xb, cl, cr, yps);
        load6(vx, rb, xb, cl, cr, vxs);
        load6(vy, rb, xb, cl, cr, vys);
        load6(Fx, rb, xb, cl, cr, fxs);
        load6(Fy, rb, xb, cl, cr, fys);

        #pragma unroll
        for (int s = 0; s < 6; ++s) {
            // row-direction tent weight (shared across this source's dsts)
            float dyv = yps[s] - fy0;
            float ny  = fmaxf(1.0f - fabsf(dyv), 0.0f);

            const int kmin = (s - 2 > 0) ? (s - 2) : 0;
            const int kmax = (s < 3) ? s : 3;
            #pragma unroll
            for (int k = kmin; k <= kmax; ++k) {
                float dxv = xps[s] - xdst[k];
                float nx  = fmaxf(1.0f - fabsf(dxv), 0.0f);
                float w   = ny * nx;
                aA[k] += w;
                aU[k] = fmaf(w, vxs[s], aU[k]);
                aV[k] = fmaf(w, vys[s], aV[k]);
                aX[k] = fmaf(w, fxs[s], aX[k]);
                aY[k] = fmaf(w, fys[s], aY[k]);
            }
        }
    }

    // Destination-side factor: mask_dst * VP (mask is NOT rolled in the ref).
    size_t o = ((size_t)y << 12) + xb;
    float4 mq = *reinterpret_cast<const float4*>(mk + o);
    float md[4] = {mq.x * VP, mq.y * VP, mq.z * VP, mq.w * VP};

    #pragma unroll
    for (int k = 0; k < 4; ++k) {
        aA[k] *= md[k]; aU[k] *= md[k]; aV[k] *= md[k];
        aX[k] *= md[k]; aY[k] *= md[k];
    }

    const size_t P = (size_t)NXD * NXD;
    *reinterpret_cast<float4*>(out + o)         = make_float4(aA[0], aA[1], aA[2], aA[3]);
    *reinterpret_cast<float4*>(out + P + o)     = make_float4(aU[0], aU[1], aU[2], aU[3]);
    *reinterpret_cast<float4*>(out + 2 * P + o) = make_float4(aV[0], aV[1], aV[2], aV[3]);
    *reinterpret_cast<float4*>(out + 3 * P + o) = make_float4(aX[0], aX[1], aX[2], aX[3]);
    *reinterpret_cast<float4*>(out + 4 * P + o) = make_float4(aY[0], aY[1], aY[2], aY[3]);
}

extern "C" void kernel_launch(void* const* d_in, const int* in_sizes, int n_in,
                              void* d_out, int out_size)
{
    const float* xp = (const float*)d_in[0];
    const float* yp = (const float*)d_in[1];
    // d_in[2] = x_grid, d_in[3] = y_grid: analytic (x, y), not needed.
    const float* vx = (const float*)d_in[4];
    const float* vy = (const float*)d_in[5];
    const float* Fx = (const float*)d_in[6];
    const float* Fy = (const float*)d_in[7];
    const float* mk = (const float*)d_in[8];
    float* out = (float*)d_out;

    const int total = 4096 * 1024;     // one thread per 4 outputs
    const int block = 256;
    ai4dem_kernel<<<total / block, block>>>(xp, yp, vx, vy, Fx, Fy, mk, out);
}